// round 1
// baseline (speedup 1.0000x reference)
#include <cuda_runtime.h>

#define MAX_N 50000
#define MAX_E 800000
#define C 64

// ---------- scratch (device globals; no allocation allowed) ----------
__device__ float    g_h[(size_t)MAX_N * C];       // h = x @ W^T
__device__ float    g_si[MAX_N];
__device__ float    g_sj[MAX_N];
__device__ unsigned g_amax[MAX_N];                // order-mapped float max
__device__ float    g_denom[MAX_N];
__device__ float    g_alpha[MAX_E + MAX_N];       // edge logits, then exp()

// order-preserving float<->uint map for atomicMax
__device__ __forceinline__ unsigned fmap(float f) {
    unsigned u = __float_as_uint(f);
    return (u & 0x80000000u) ? ~u : (u | 0x80000000u);
}
__device__ __forceinline__ float funmap(unsigned u) {
    u = (u & 0x80000000u) ? (u & 0x7fffffffu) : ~u;
    return __uint_as_float(u);
}

// ---------- K1: h = x W^T, s_i, s_j, init out=bias / amax / denom ----------
__global__ void k1_project(const float* __restrict__ x,
                           const float* __restrict__ emb,
                           const float* __restrict__ W,
                           const float* __restrict__ att_i,
                           const float* __restrict__ att_j,
                           const float* __restrict__ att_em_i,
                           const float* __restrict__ att_em_j,
                           const float* __restrict__ bias,
                           float* __restrict__ out, int N)
{
    __shared__ float Ws[C][C + 1];   // +1 pad: conflict-free column access
    __shared__ float xs[4][C];
    __shared__ float red_i[8], red_j[8];

    int tid = threadIdx.x;           // 256 threads: 4 nodes x 64 channels
    for (int i = tid; i < C * C; i += 256) Ws[i / C][i % C] = W[i];

    int ln = tid >> 6;               // local node 0..3
    int c  = tid & 63;               // channel
    int n  = blockIdx.x * 4 + ln;
    if (n < N) xs[ln][c] = x[(size_t)n * C + c];
    __syncthreads();
    if (n >= N) return;

    float acc = 0.f;
#pragma unroll
    for (int k = 0; k < C; k++) acc = fmaf(xs[ln][k], Ws[c][k], acc);

    g_h[(size_t)n * C + c] = acc;
    out[(size_t)n * C + c] = bias[c];    // atomics accumulate on top

    float e  = emb[(size_t)n * C + c];
    float pi = acc * att_i[c] + e * att_em_i[c];
    float pj = acc * att_j[c] + e * att_em_j[c];
#pragma unroll
    for (int o = 16; o; o >>= 1) {
        pi += __shfl_down_sync(0xffffffffu, pi, o);
        pj += __shfl_down_sync(0xffffffffu, pj, o);
    }
    int w = tid >> 5;                // warp 0..7 (2 warps per node)
    if ((tid & 31) == 0) { red_i[w] = pi; red_j[w] = pj; }
    __syncthreads();
    if (c == 0) {
        g_si[n]   = red_i[2 * ln] + red_i[2 * ln + 1];
        g_sj[n]   = red_j[2 * ln] + red_j[2 * ln + 1];
        g_amax[n] = 0u;              // below fmap(-inf)
        g_denom[n] = 0.f;
    }
}

// ---------- K2: edge logits + segment max ----------
__global__ void k2_max(const int* __restrict__ ei, int E, int N)
{
    int e = blockIdx.x * blockDim.x + threadIdx.x;
    int EN = E + N;
    if (e >= EN) return;
    int s, d;
    if (e < E) { s = ei[e]; d = ei[E + e]; }
    else       { s = d = e - E; }
    float a = g_si[d] + g_sj[s];
    a = (a > 0.f) ? a : 0.2f * a;    // leaky_relu, slope 0.2
    g_alpha[e] = a;
    atomicMax(&g_amax[d], fmap(a));
}

// ---------- K3: exp + segment sum ----------
__global__ void k3_sum(const int* __restrict__ ei, int E, int N)
{
    int e = blockIdx.x * blockDim.x + threadIdx.x;
    int EN = E + N;
    if (e >= EN) return;
    int d = (e < E) ? ei[E + e] : (e - E);
    float ex = __expf(g_alpha[e] - funmap(g_amax[d]));
    g_alpha[e] = ex;
    atomicAdd(&g_denom[d], ex);
}

// ---------- K4: weighted message scatter (16 threads / edge, float4 RED) ----------
__global__ void k4_scatter(const int* __restrict__ ei, float* __restrict__ out,
                           int E, int N)
{
    unsigned t = blockIdx.x * blockDim.x + threadIdx.x;
    int e    = (int)(t >> 4);
    int part = (int)(t & 15);
    int EN = E + N;
    if (e >= EN) return;
    int s, d;
    if (e < E) { s = ei[e]; d = ei[E + e]; }
    else       { s = d = e - E; }
    float w = g_alpha[e] / (g_denom[d] + 1e-16f);

    const float4 hv = *reinterpret_cast<const float4*>(&g_h[(size_t)s * C + part * 4]);
    float4 m;
    m.x = hv.x * w; m.y = hv.y * w; m.z = hv.z * w; m.w = hv.w * w;

    float* p = &out[(size_t)d * C + part * 4];
    asm volatile("red.global.add.v4.f32 [%0], {%1,%2,%3,%4};"
                 :: "l"(p), "f"(m.x), "f"(m.y), "f"(m.z), "f"(m.w)
                 : "memory");
}

// ---------- K5: final ReLU ----------
__global__ void k5_relu(float4* __restrict__ out, int n4)
{
    int i = blockIdx.x * blockDim.x + threadIdx.x;
    if (i >= n4) return;
    float4 v = out[i];
    v.x = fmaxf(v.x, 0.f); v.y = fmaxf(v.y, 0.f);
    v.z = fmaxf(v.z, 0.f); v.w = fmaxf(v.w, 0.f);
    out[i] = v;
}

extern "C" void kernel_launch(void* const* d_in, const int* in_sizes, int n_in,
                              void* d_out, int out_size)
{
    const float* x        = (const float*)d_in[0];
    const int*   ei       = (const int*)  d_in[1];
    const float* emb      = (const float*)d_in[2];
    const float* W        = (const float*)d_in[3];
    const float* att_i    = (const float*)d_in[4];
    const float* att_j    = (const float*)d_in[5];
    const float* att_em_i = (const float*)d_in[6];
    const float* att_em_j = (const float*)d_in[7];
    const float* bias     = (const float*)d_in[8];
    float* out = (float*)d_out;

    int N = in_sizes[0] / C;
    int E = in_sizes[1] / 2;
    int EN = E + N;

    k1_project<<<(N + 3) / 4, 256>>>(x, emb, W, att_i, att_j, att_em_i, att_em_j,
                                     bias, out, N);
    k2_max<<<(EN + 255) / 256, 256>>>(ei, E, N);
    k3_sum<<<(EN + 255) / 256, 256>>>(ei, E, N);
    unsigned t4 = (unsigned)EN * 16u;
    k4_scatter<<<(t4 + 255) / 256, 256>>>(ei, out, E, N);
    int n4 = out_size / 4;
    k5_relu<<<(n4 + 255) / 256, 256>>>((float4*)out, n4);
}

// round 2
// speedup vs baseline: 2.2169x; 2.2169x over previous
#include <cuda_runtime.h>

#define C 64
#define MAX_N 50000

// ---------- scratch (device globals; no allocation allowed) ----------
__device__ float g_h[(size_t)MAX_N * C];   // h = x @ W^T
__device__ float g_si[MAX_N];
__device__ float g_sj[MAX_N];
__device__ float g_denom[MAX_N];

// ---------- K1: h = x W^T, s_i, s_j, init out=0 / denom=0 ----------
// block = 256 threads, 16 nodes/block. c = t&63, node-group ng = t>>6 (4 nodes each)
__global__ void k1_project(const float* __restrict__ x,
                           const float* __restrict__ emb,
                           const float* __restrict__ W,
                           const float* __restrict__ att_i,
                           const float* __restrict__ att_j,
                           const float* __restrict__ att_em_i,
                           const float* __restrict__ att_em_j,
                           float* __restrict__ out, int N)
{
    __shared__ float Ws[C][C + 4];          // +4 floats: conflict-free LDS.128
    __shared__ float xs[16][C];
    __shared__ float red_i[16][2], red_j[16][2];

    int t  = threadIdx.x;
    int c  = t & 63;
    int ng = t >> 6;                        // 0..3
    int nb = blockIdx.x * 16;

    for (int i = t; i < C * C; i += 256) Ws[i >> 6][i & 63] = W[i];
    for (int i = t; i < 16 * C / 4; i += 256) {
        int node = i >> 4, q = i & 15;
        int n = nb + node;
        float4 v = (n < N) ? ((const float4*)x)[(size_t)n * 16 + q]
                           : make_float4(0.f, 0.f, 0.f, 0.f);
        ((float4*)xs[node])[q] = v;
    }
    __syncthreads();

    int n0 = ng * 4;
    float acc[4] = {0.f, 0.f, 0.f, 0.f};
    const float4* wrow = (const float4*)Ws[c];
#pragma unroll
    for (int kq = 0; kq < 16; kq++) {
        float4 w4 = wrow[kq];
        float4 a0 = ((const float4*)xs[n0 + 0])[kq];
        float4 a1 = ((const float4*)xs[n0 + 1])[kq];
        float4 a2 = ((const float4*)xs[n0 + 2])[kq];
        float4 a3 = ((const float4*)xs[n0 + 3])[kq];
        acc[0] = fmaf(a0.x, w4.x, fmaf(a0.y, w4.y, fmaf(a0.z, w4.z, fmaf(a0.w, w4.w, acc[0]))));
        acc[1] = fmaf(a1.x, w4.x, fmaf(a1.y, w4.y, fmaf(a1.z, w4.z, fmaf(a1.w, w4.w, acc[1]))));
        acc[2] = fmaf(a2.x, w4.x, fmaf(a2.y, w4.y, fmaf(a2.z, w4.z, fmaf(a2.w, w4.w, acc[2]))));
        acc[3] = fmaf(a3.x, w4.x, fmaf(a3.y, w4.y, fmaf(a3.z, w4.z, fmaf(a3.w, w4.w, acc[3]))));
    }

    float atti = att_i[c], attj = att_j[c];
    float aemi = att_em_i[c], aemj = att_em_j[c];
    int lane = t & 31;
    int half = (t >> 5) & 1;                // c<32 / c>=32

#pragma unroll
    for (int i = 0; i < 4; i++) {
        int n = nb + n0 + i;
        if (n >= N) continue;
        g_h[((size_t)n << 6) + c] = acc[i];
        out[((size_t)n << 6) + c] = 0.f;
        float e  = emb[((size_t)n << 6) + c];
        float pi = acc[i] * atti + e * aemi;
        float pj = acc[i] * attj + e * aemj;
#pragma unroll
        for (int o = 16; o; o >>= 1) {
            pi += __shfl_down_sync(0xffffffffu, pi, o);
            pj += __shfl_down_sync(0xffffffffu, pj, o);
        }
        if (lane == 0) { red_i[n0 + i][half] = pi; red_j[n0 + i][half] = pj; }
    }
    __syncthreads();
    if (t < 16) {
        int n = nb + t;
        if (n < N) {
            g_si[n]    = red_i[t][0] + red_i[t][1];
            g_sj[n]    = red_j[t][0] + red_j[t][1];
            g_denom[n] = 0.f;
        }
    }
}

// ---------- K2: fused edge pass: exp logits, denom atomicAdd, message scatter ----------
// 16 lanes / edge; leader lane (part==0) computes scalars, shfl-broadcasts
__global__ void k2_edge(const int* __restrict__ ei, float* __restrict__ out,
                        int E, int N)
{
    unsigned t = blockIdx.x * blockDim.x + threadIdx.x;
    int e    = (int)(t >> 4);
    int part = (int)(t & 15);
    int lane = threadIdx.x & 31;
    int EN = E + N;
    bool valid = (e < EN);

    int s = 0, d = 0; float ex = 0.f;
    if (valid && part == 0) {
        if (e < E) { s = __ldg(&ei[e]); d = __ldg(&ei[E + e]); }
        else       { s = d = e - E; }
        float a = g_si[d] + g_sj[s];
        a = (a > 0.f) ? a : 0.2f * a;       // leaky_relu, slope 0.2
        ex = __expf(a);                      // no max-shift: softmax shift-invariant
        atomicAdd(&g_denom[d], ex);
    }
    int srcl = lane & 16;
    s  = __shfl_sync(0xffffffffu, s,  srcl);
    d  = __shfl_sync(0xffffffffu, d,  srcl);
    ex = __shfl_sync(0xffffffffu, ex, srcl);
    if (!valid) return;

    float4 hv = *reinterpret_cast<const float4*>(&g_h[((size_t)s << 6) + (part << 2)]);
    float* p = &out[((size_t)d << 6) + (part << 2)];
    asm volatile("red.global.add.v4.f32 [%0], {%1,%2,%3,%4};"
                 :: "l"(p), "f"(hv.x * ex), "f"(hv.y * ex),
                    "f"(hv.z * ex), "f"(hv.w * ex)
                 : "memory");
}

// ---------- K3: normalize by denom, add bias, ReLU ----------
__global__ void k3_final(float4* __restrict__ out, const float* __restrict__ bias,
                         int N)
{
    int i = blockIdx.x * blockDim.x + threadIdx.x;
    if (i >= N * 16) return;
    int n = i >> 4, q = i & 15;
    float4 v = out[i];
    float r = 1.f / (g_denom[n] + 1e-16f);
    float4 b = ((const float4*)bias)[q];
    v.x = fmaxf(fmaf(v.x, r, b.x), 0.f);
    v.y = fmaxf(fmaf(v.y, r, b.y), 0.f);
    v.z = fmaxf(fmaf(v.z, r, b.z), 0.f);
    v.w = fmaxf(fmaf(v.w, r, b.w), 0.f);
    out[i] = v;
}

extern "C" void kernel_launch(void* const* d_in, const int* in_sizes, int n_in,
                              void* d_out, int out_size)
{
    const float* x        = (const float*)d_in[0];
    const int*   ei       = (const int*)  d_in[1];
    const float* emb      = (const float*)d_in[2];
    const float* W        = (const float*)d_in[3];
    const float* att_i    = (const float*)d_in[4];
    const float* att_j    = (const float*)d_in[5];
    const float* att_em_i = (const float*)d_in[6];
    const float* att_em_j = (const float*)d_in[7];
    const float* bias     = (const float*)d_in[8];
    float* out = (float*)d_out;

    int N  = in_sizes[0] / C;
    int E  = in_sizes[1] / 2;
    int EN = E + N;

    k1_project<<<(N + 15) / 16, 256>>>(x, emb, W, att_i, att_j, att_em_i,
                                       att_em_j, out, N);
    unsigned t2 = (unsigned)EN * 16u;
    k2_edge<<<(t2 + 255) / 256, 256>>>(ei, out, E, N);
    k3_final<<<(N * 16 + 255) / 256, 256>>>((float4*)out, bias, N);
}

// round 4
// speedup vs baseline: 2.5114x; 1.1329x over previous
#include <cuda_runtime.h>

#define C 64
#define MAX_N 50000
#define NPB 96              // nodes per block in k1
#define XR 68               // padded row stride (floats) for xs/wt

// ---------- scratch (device globals; no allocation allowed) ----------
__device__ float g_h[(size_t)MAX_N * C];   // h = x @ W^T
__device__ float g_si[MAX_N];
__device__ float g_sj[MAX_N];
__device__ float g_denom[MAX_N];

// ---------- K0: zero the output (atomics accumulate on top) ----------
__global__ void k0_zero(float4* __restrict__ out, int n4)
{
    int i = blockIdx.x * blockDim.x + threadIdx.x;
    if (i < n4) out[i] = make_float4(0.f, 0.f, 0.f, 0.f);
}

// ---------- K1: h = x W^T, s_i, s_j, denom=0 ----------
// 256 threads. c_slot = t&15 (4 channels), node slot = t>>4 (6 nodes, stride 16).
__global__ void k1_project(const float* __restrict__ x,
                           const float* __restrict__ emb,
                           const float* __restrict__ W,
                           const float* __restrict__ att_i,
                           const float* __restrict__ att_j,
                           const float* __restrict__ att_em_i,
                           const float* __restrict__ att_em_j,
                           int N)
{
    __shared__ float xs[NPB * XR];      // [local node][k]
    __shared__ float wt[C * XR];        // [k][c]  (W transposed)

    int t  = threadIdx.x;
    int nb = blockIdx.x * NPB;

    // fill Wt (coalesced read of W; strided STS once per block)
    for (int idx = t; idx < C * C; idx += 256) {
        int c = idx >> 6, k = idx & 63;
        wt[k * XR + c] = W[idx];
    }
    // fill xs (float4, zero-pad OOB nodes)
    for (int idx = t; idx < NPB * 16; idx += 256) {
        int node = idx >> 4, q = idx & 15;
        int n = nb + node;
        float4 v = (n < N) ? ((const float4*)x)[(size_t)n * 16 + q]
                           : make_float4(0.f, 0.f, 0.f, 0.f);
        *(float4*)&xs[node * XR + q * 4] = v;
    }
    __syncthreads();

    int c_slot = t & 15;
    int slot   = t >> 4;

    float acc[6][4];
#pragma unroll
    for (int i = 0; i < 6; i++)
#pragma unroll
        for (int j = 0; j < 4; j++) acc[i][j] = 0.f;

    const float* wp = &wt[c_slot * 4];
    const float* xp = &xs[slot * XR];

#pragma unroll 4
    for (int k = 0; k < C; k++) {
        float4 w4 = *(const float4*)&wp[k * XR];
#pragma unroll
        for (int i = 0; i < 6; i++) {
            float xk = xp[i * (16 * XR) + k];
            acc[i][0] = fmaf(xk, w4.x, acc[i][0]);
            acc[i][1] = fmaf(xk, w4.y, acc[i][1]);
            acc[i][2] = fmaf(xk, w4.z, acc[i][2]);
            acc[i][3] = fmaf(xk, w4.w, acc[i][3]);
        }
    }

    float4 ai  = ((const float4*)att_i)[c_slot];
    float4 aj  = ((const float4*)att_j)[c_slot];
    float4 aei = ((const float4*)att_em_i)[c_slot];
    float4 aej = ((const float4*)att_em_j)[c_slot];

#pragma unroll
    for (int i = 0; i < 6; i++) {
        int n = nb + slot + 16 * i;
        bool ok = (n < N);
        float4 a = make_float4(acc[i][0], acc[i][1], acc[i][2], acc[i][3]);
        float4 e = ok ? ((const float4*)emb)[(size_t)n * 16 + c_slot]
                      : make_float4(0.f, 0.f, 0.f, 0.f);
        if (ok) ((float4*)g_h)[(size_t)n * 16 + c_slot] = a;

        float pi = a.x*ai.x + a.y*ai.y + a.z*ai.z + a.w*ai.w
                 + e.x*aei.x + e.y*aei.y + e.z*aei.z + e.w*aei.w;
        float pj = a.x*aj.x + a.y*aj.y + a.z*aj.z + a.w*aj.w
                 + e.x*aej.x + e.y*aej.y + e.z*aej.z + e.w*aej.w;
#pragma unroll
        for (int o = 8; o; o >>= 1) {
            pi += __shfl_xor_sync(0xffffffffu, pi, o);
            pj += __shfl_xor_sync(0xffffffffu, pj, o);
        }
        if (ok && c_slot == 0) { g_si[n] = pi; g_sj[n] = pj; }
    }

    if (t < NPB) {
        int n = nb + t;
        if (n < N) g_denom[n] = 0.f;
    }
}

// ---------- K2: fused edge pass: exp logits, denom atomicAdd, message scatter ----------
__global__ void k2_edge(const int* __restrict__ ei, float* __restrict__ out,
                        int E, int N)
{
    unsigned t = blockIdx.x * blockDim.x + threadIdx.x;
    int e    = (int)(t >> 4);
    int part = (int)(t & 15);
    int lane = threadIdx.x & 31;
    int EN = E + N;
    bool valid = (e < EN);

    int s = 0, d = 0; float ex = 0.f;
    if (valid && part == 0) {
        if (e < E) { s = __ldg(&ei[e]); d = __ldg(&ei[E + e]); }
        else       { s = d = e - E; }
        float a = g_si[d] + g_sj[s];
        a = (a > 0.f) ? a : 0.2f * a;       // leaky_relu, slope 0.2
        ex = __expf(a);                      // softmax shift-invariance: no max pass
        atomicAdd(&g_denom[d], ex);
    }
    int srcl = lane & 16;
    s  = __shfl_sync(0xffffffffu, s,  srcl);
    d  = __shfl_sync(0xffffffffu, d,  srcl);
    ex = __shfl_sync(0xffffffffu, ex, srcl);
    if (!valid) return;

    float4 hv = *reinterpret_cast<const float4*>(&g_h[((size_t)s << 6) + (part << 2)]);
    float* p = &out[((size_t)d << 6) + (part << 2)];
    asm volatile("red.global.add.v4.f32 [%0], {%1,%2,%3,%4};"
                 :: "l"(p), "f"(hv.x * ex), "f"(hv.y * ex),
                    "f"(hv.z * ex), "f"(hv.w * ex)
                 : "memory");
}

// ---------- K3: normalize by denom, add bias, ReLU ----------
__global__ void k3_final(float4* __restrict__ out, const float* __restrict__ bias,
                         int N)
{
    int i = blockIdx.x * blockDim.x + threadIdx.x;
    if (i >= N * 16) return;
    int n = i >> 4, q = i & 15;
    float4 v = out[i];
    float r = 1.f / (g_denom[n] + 1e-16f);
    float4 b = ((const float4*)bias)[q];
    v.x = fmaxf(fmaf(v.x, r, b.x), 0.f);
    v.y = fmaxf(fmaf(v.y, r, b.y), 0.f);
    v.z = fmaxf(fmaf(v.z, r, b.z), 0.f);
    v.w = fmaxf(fmaf(v.w, r, b.w), 0.f);
    out[i] = v;
}

extern "C" void kernel_launch(void* const* d_in, const int* in_sizes, int n_in,
                              void* d_out, int out_size)
{
    const float* x        = (const float*)d_in[0];
    const int*   ei       = (const int*)  d_in[1];
    const float* emb      = (const float*)d_in[2];
    const float* W        = (const float*)d_in[3];
    const float* att_i    = (const float*)d_in[4];
    const float* att_j    = (const float*)d_in[5];
    const float* att_em_i = (const float*)d_in[6];
    const float* att_em_j = (const float*)d_in[7];
    const float* bias     = (const float*)d_in[8];
    float* out = (float*)d_out;

    int N  = in_sizes[0] / C;
    int E  = in_sizes[1] / 2;
    int EN = E + N;

    int n4 = out_size / 4;
    k0_zero<<<(n4 + 255) / 256, 256>>>((float4*)out, n4);
    k1_project<<<(N + NPB - 1) / NPB, 256>>>(x, emb, W, att_i, att_j,
                                             att_em_i, att_em_j, N);
    unsigned t2 = (unsigned)EN * 16u;
    k2_edge<<<(t2 + 255) / 256, 256>>>(ei, out, E, N);
    k3_final<<<(N * 16 + 255) / 256, 256>>>((float4*)out, bias, N);
}